// round 15
// baseline (speedup 1.0000x reference)
#include <cuda_runtime.h>
#include <cuda_bf16.h>
#include <math.h>
#include <stdint.h>

#define BATCH    32768
#define DIM      256
#define MAX_IT   40
#define PCTAS    256               // persistent grid (4, 64)
#define YF_ELEMS (2048*16*2*32)    // [mtile][kk16][half][lane] uint4
#define XS_ELEMS (BATCH*128)       // [row*128 + col/2] uint2
#define WS_BYTES 65536             // 4096 uint4: [kk][n8l][lane]

// ---------------- device scratch ----------------
__device__ uint4 g_yf[2][YF_ELEMS];     // y as A-fragments (hi,hi,lo,lo), ping-pong
__device__ uint2 g_xs[2][XS_ELEMS];     // x as interleaved bf16 splits, ping-pong
__device__ uint2 g_bs[XS_ELEMS];        // b as interleaved bf16 splits
__device__ uint4 g_wf[16*32*32];        // W as B-fragments [kk][n8][lane]
__device__ uint4 g_uf[16*32*32];        // U^T as B-fragments
__device__ __nv_bfloat16 g_w0[DIM*DIM];
__device__ __nv_bfloat16 g_w1[DIM*DIM];
__device__ __nv_bfloat16 g_u0[DIM*DIM];
__device__ __nv_bfloat16 g_u1[DIM*DIM];
__device__ float g_part[2][PCTAS*2];    // per-pass-parity CTA partials
__device__ int   g_barc;                // grid barrier arrive counter
__device__ volatile int g_barg;         // grid barrier generation

// ---------------- helpers ----------------
__device__ __forceinline__ uint32_t bpack(__nv_bfloat16 a, __nv_bfloat16 b) {
    uint16_t ua = *(uint16_t*)&a, ub = *(uint16_t*)&b;
    return (uint32_t)ua | ((uint32_t)ub << 16);
}
__device__ __forceinline__ float2 bunpack(uint32_t u) {
    __nv_bfloat162 h = *(__nv_bfloat162*)&u;
    return make_float2(__bfloat162float(h.x), __bfloat162float(h.y));
}
__device__ __forceinline__ float2 sunpack(uint2 u) {
    float2 h = bunpack(u.x), l = bunpack(u.y);
    return make_float2(h.x + l.x, h.y + l.y);
}
__device__ __forceinline__ uint32_t split_hi(float a, float b,
                                             float& ra, float& rb) {
    __nv_bfloat16 ha = __float2bfloat16(a), hb = __float2bfloat16(b);
    ra = a - __bfloat162float(ha);
    rb = b - __bfloat162float(hb);
    return bpack(ha, hb);
}
__device__ __forceinline__ uint32_t pack_lo(float ra, float rb) {
    return bpack(__float2bfloat16(ra), __float2bfloat16(rb));
}
__device__ __forceinline__ void mma_bf16(float* c, const uint32_t* a, const uint32_t* b) {
    asm volatile(
        "mma.sync.aligned.m16n8k16.row.col.f32.bf16.bf16.f32 "
        "{%0,%1,%2,%3}, {%4,%5,%6,%7}, {%8,%9}, {%0,%1,%2,%3};"
        : "+f"(c[0]), "+f"(c[1]), "+f"(c[2]), "+f"(c[3])
        : "r"(a[0]), "r"(a[1]), "r"(a[2]), "r"(a[3]), "r"(b[0]), "r"(b[1]));
}

// ---------------- prep: Weff and U^T -> bf16 splits ----------
__global__ void prep_kernel(const float* __restrict__ U,
                            const float* __restrict__ A,
                            const float* __restrict__ B) {
    int i = blockIdx.x;    // k
    int j = threadIdx.x;   // n
    float u = U[j*DIM + i];
    __nv_bfloat16 uh = __float2bfloat16(u);
    g_u0[i*DIM + j] = uh;
    g_u1[i*DIM + j] = __float2bfloat16(u - __bfloat162float(uh));
    float s = 0.f;
#pragma unroll 8
    for (int p = 0; p < DIM; ++p)
        s = fmaf(A[p*DIM + i], A[p*DIM + j], s);
    float w = -s + B[j*DIM + i] - B[i*DIM + j];
    if (i == j) w += 0.8f;                    // (1-m), m=0.2
    __nv_bfloat16 h0 = __float2bfloat16(w);
    g_w0[i*DIM + j] = h0;
    g_w1[i*DIM + j] = __float2bfloat16(w - __bfloat162float(h0));
}

// ---------------- prep2: pack W and U^T into B-fragment order ----------------
__global__ void prep2_kernel() {
    int kk = blockIdx.x, n8 = blockIdx.y, lane = threadIdx.x;
    int k0 = kk*16 + 2*(lane & 3);
    int n  = n8*8 + (lane >> 2);
    int o  = (kk*32 + n8)*32 + lane;
    uint4 u;
    u.x = bpack(g_w0[(k0    )*DIM + n], g_w0[(k0+1)*DIM + n]);
    u.y = bpack(g_w0[(k0 + 8)*DIM + n], g_w0[(k0+9)*DIM + n]);
    u.z = bpack(g_w1[(k0    )*DIM + n], g_w1[(k0+1)*DIM + n]);
    u.w = bpack(g_w1[(k0 + 8)*DIM + n], g_w1[(k0+9)*DIM + n]);
    g_wf[o] = u;
    u.x = bpack(g_u0[(k0    )*DIM + n], g_u0[(k0+1)*DIM + n]);
    u.y = bpack(g_u0[(k0 + 8)*DIM + n], g_u0[(k0+9)*DIM + n]);
    u.z = bpack(g_u1[(k0    )*DIM + n], g_u1[(k0+1)*DIM + n]);
    u.w = bpack(g_u1[(k0 + 8)*DIM + n], g_u1[(k0+9)*DIM + n]);
    g_uf[o] = u;
}

// ---------------- flags: reset barrier state ----------------
__global__ void flags_kernel() {
    if (threadIdx.x == 0) { g_barc = 0; g_barg = 0; }
}

// ---------------- packx: input x -> A-fragments in g_yf[0] (scratch) --------
__global__ void packx_kernel(const float* __restrict__ xin) {
    int idx  = blockIdx.x * blockDim.x + threadIdx.x;
    int lane = idx & 31;
    int k8   = (idx >> 5) & 31;
    int mt   = idx >> 10;
    int row0 = mt*16 + (lane >> 2);
    int col  = k8*8 + (lane & 3)*2;
    int gi0  = row0*DIM + col, gi1 = gi0 + 8*DIM;
    float2 v0 = *(const float2*)(xin + gi0);
    float2 v1 = *(const float2*)(xin + gi1);
    float r0, r1, r2, r3;
    uint32_t h0 = split_hi(v0.x, v0.y, r0, r1);
    uint32_t h1 = split_hi(v1.x, v1.y, r2, r3);
    int yidx = ((mt*16 + (k8 >> 1))*2 + (k8 & 1))*32 + lane;
    g_yf[0][yidx] = make_uint4(h0, h1, pack_lo(r0, r1), pack_lo(r2, r3));
}

// ---------------- bias GEMM (tensor): b = x @ U^T + ub -> split storage ------
__global__ void __launch_bounds__(256, 3)
bias_tensor(const float* __restrict__ ub) {
    extern __shared__ __align__(16) uint4 ws[];
    const int tid  = threadIdx.x;
    const int lane = tid & 31;
    const int wid  = tid >> 5;
    const int wm   = wid & 3;
    const int wn   = wid >> 2;
    const int mb   = blockIdx.y;
    const int nb   = blockIdx.x;

#pragma unroll
    for (int j = 0; j < 16; ++j) {
        int linear = j*256 + tid;
        int l  = linear & 31;
        int r  = linear >> 5;
        int kk = r >> 3, n8l = r & 7;
        ws[linear] = g_uf[kk*1024 + (nb*8 + n8l)*32 + l];
    }
    __syncthreads();

    const uint4* __restrict__ yf = g_yf[0];
    float acc[2][4][4];
#pragma unroll
    for (int mi = 0; mi < 2; ++mi)
#pragma unroll
        for (int ni = 0; ni < 4; ++ni)
#pragma unroll
            for (int q = 0; q < 4; ++q) acc[mi][ni][q] = 0.f;
    const int mt0 = mb*8 + wm*2;
#pragma unroll
    for (int kk = 0; kk < 16; ++kk) {
        uint32_t ah[2][4], al[2][4];
#pragma unroll
        for (int mi = 0; mi < 2; ++mi) {
            int base = (((mt0 + mi)*16 + kk)*2)*32 + lane;
            uint4 u0 = yf[base];
            uint4 u1 = yf[base + 32];
            ah[mi][0] = u0.x; ah[mi][1] = u0.y; ah[mi][2] = u1.x; ah[mi][3] = u1.y;
            al[mi][0] = u0.z; al[mi][1] = u0.w; al[mi][2] = u1.z; al[mi][3] = u1.w;
        }
#pragma unroll
        for (int ni = 0; ni < 4; ++ni) {
            uint4 u = ws[(kk*8 + wn*4 + ni)*32 + lane];
            uint32_t bh[2] = {u.x, u.y};
            uint32_t bl[2] = {u.z, u.w};
#pragma unroll
            for (int mi = 0; mi < 2; ++mi) {
                float* c = acc[mi][ni];
                mma_bf16(c, ah[mi], bh);
                mma_bf16(c, al[mi], bh);
                mma_bf16(c, ah[mi], bl);
            }
        }
    }
    const int t2 = lane & 3, g = lane >> 2;
#pragma unroll
    for (int mi = 0; mi < 2; ++mi) {
        int row0 = mb*128 + wm*32 + mi*16 + g;
#pragma unroll
        for (int ni = 0; ni < 4; ++ni) {
            int k8  = nb*8 + wn*4 + ni;
            int col = k8*8 + t2*2;
            int gi0 = row0*DIM + col, gi1 = gi0 + 8*DIM;
            float2 u = *(const float2*)(ub + col);
            float b00 = acc[mi][ni][0] + u.x, b01 = acc[mi][ni][1] + u.y;
            float b10 = acc[mi][ni][2] + u.x, b11 = acc[mi][ni][3] + u.y;
            float r0, r1, r2, r3;
            uint32_t h0 = split_hi(b00, b01, r0, r1);
            g_bs[gi0 >> 1] = make_uint2(h0, pack_lo(r0, r1));
            uint32_t h1 = split_hi(b10, b11, r2, r3);
            g_bs[gi1 >> 1] = make_uint2(h1, pack_lo(r2, r3));
        }
    }
}

// ---------------- start: body 1 analytically (y0=x0=0, beta1=0) --------------
__global__ void start_kernel() {
    int idx  = blockIdx.x * blockDim.x + threadIdx.x;
    int lane = idx & 31;
    int k8   = (idx >> 5) & 31;
    int mt   = idx >> 10;
    int row0 = mt*16 + (lane >> 2);
    int col  = k8*8 + (lane & 3)*2;
    int gi0  = row0*DIM + col, gi1 = gi0 + 8*DIM;
    float2 b0 = sunpack(g_bs[gi0 >> 1]);
    float2 b1 = sunpack(g_bs[gi1 >> 1]);
    float v00 = fmaxf(0.5f*b0.x, 0.f), v01 = fmaxf(0.5f*b0.y, 0.f);
    float v10 = fmaxf(0.5f*b1.x, 0.f), v11 = fmaxf(0.5f*b1.y, 0.f);
    float r0, r1, r2, r3;
    uint32_t h0 = split_hi(v00, v01, r0, r1);
    uint32_t l0 = pack_lo(r0, r1);
    uint32_t h1 = split_hi(v10, v11, r2, r3);
    uint32_t l1 = pack_lo(r2, r3);
    int yidx = ((mt*16 + (k8 >> 1))*2 + (k8 & 1))*32 + lane;
    g_yf[1][yidx] = make_uint4(h0, h1, l0, l1);
    g_xs[1][gi0 >> 1] = make_uint2(h0, l0);
    g_xs[1][gi1 >> 1] = make_uint2(h1, l1);
}

// ---------------- persistent kernel: bodies 2..40 + final output -------------
__global__ void __launch_bounds__(256, 3)
persist_kernel(float* __restrict__ outp) {
    extern __shared__ __align__(16) uint4 ws[];
    __shared__ float redsm[16];
    __shared__ float errsm;
    const int tid  = threadIdx.x;
    const int lane = tid & 31;
    const int wid  = tid >> 5;
    const int wm   = wid & 3;
    const int wn   = wid >> 2;
    const int nb   = blockIdx.x;   // 0..3 (fixed N slice)
    const int jb   = blockIdx.y;   // 0..63 (4 mb tiles each)
    const int cta  = jb*4 + nb;
    const int t2 = lane & 3, g = lane >> 2;

    // ---- stage W slice ONCE ----
#pragma unroll
    for (int j = 0; j < 16; ++j) {
        int linear = j*256 + tid;
        int l  = linear & 31;
        int r  = linear >> 5;
        int kk = r >> 3, n8l = r & 7;
        ws[linear] = g_wf[kk*1024 + (nb*8 + n8l)*32 + l];
    }
    __syncthreads();

    int par = 1, zpar = -1;
    float t = 1.6180339887f;       // t1

    for (int pass = 2; pass <= MAX_IT; ++pass) {
        float tn   = 0.5f * (1.0f + sqrtf(1.0f + 4.0f * t * t));
        float beta = (t - 1.0f) / tn;
        t = tn;
        const uint4* __restrict__ yf  = g_yf[par];
        uint4* __restrict__ yfw = g_yf[par ^ 1];
        const uint2* __restrict__ xs  = g_xs[par];
        uint2* __restrict__ xsw = g_xs[par ^ 1];
        float sn = 0.f, sd = 0.f;

#pragma unroll 1
        for (int u = 0; u < 4; ++u) {
            const int mb  = jb*4 + u;
            const int mt0 = mb*8 + wm*2;
            float acc[2][4][4];
#pragma unroll
            for (int mi = 0; mi < 2; ++mi)
#pragma unroll
                for (int ni = 0; ni < 4; ++ni)
#pragma unroll
                    for (int q = 0; q < 4; ++q) acc[mi][ni][q] = 0.f;
#pragma unroll
            for (int kk = 0; kk < 16; ++kk) {
                uint32_t ah[2][4], al[2][4];
#pragma unroll
                for (int mi = 0; mi < 2; ++mi) {
                    int base = (((mt0 + mi)*16 + kk)*2)*32 + lane;
                    uint4 u0 = yf[base];
                    uint4 u1 = yf[base + 32];
                    ah[mi][0] = u0.x; ah[mi][1] = u0.y;
                    ah[mi][2] = u1.x; ah[mi][3] = u1.y;
                    al[mi][0] = u0.z; al[mi][1] = u0.w;
                    al[mi][2] = u1.z; al[mi][3] = u1.w;
                }
#pragma unroll
                for (int ni = 0; ni < 4; ++ni) {
                    uint4 w = ws[(kk*8 + wn*4 + ni)*32 + lane];
                    uint32_t bh[2] = {w.x, w.y};
                    uint32_t bl[2] = {w.z, w.w};
#pragma unroll
                    for (int mi = 0; mi < 2; ++mi) {
                        float* c = acc[mi][ni];
                        mma_bf16(c, ah[mi], bh);
                        mma_bf16(c, al[mi], bh);
                        mma_bf16(c, ah[mi], bl);
                    }
                }
            }
            // epilogue
#pragma unroll
            for (int mi = 0; mi < 2; ++mi) {
                int row0 = mb*128 + wm*32 + mi*16 + g;
#pragma unroll
                for (int ni = 0; ni < 4; ++ni) {
                    int k8  = nb*8 + wn*4 + ni;
                    int col = k8*8 + t2*2;
                    int yidx = (((mt0 + mi)*16 + (k8 >> 1))*2 + (k8 & 1))*32 + lane;
                    uint4 yu = yf[yidx];
                    float2 a0h = bunpack(yu.x), a1h = bunpack(yu.y);
                    float2 a0l = bunpack(yu.z), a1l = bunpack(yu.w);
                    float y00 = a0h.x + a0l.x, y01 = a0h.y + a0l.y;
                    float y10 = a1h.x + a1l.x, y11 = a1h.y + a1l.y;
                    float g00 = acc[mi][ni][0], g01 = acc[mi][ni][1];
                    float g10 = acc[mi][ni][2], g11 = acc[mi][ni][3];
                    int gi0 = row0*DIM + col, gi1 = gi0 + 8*DIM;
                    float2 b0 = sunpack(g_bs[gi0 >> 1]);
                    float2 b1 = sunpack(g_bs[gi1 >> 1]);
                    float fn00 = fmaxf(g00 + b0.x, 0.f), fn01 = fmaxf(g01 + b0.y, 0.f);
                    float fn10 = fmaxf(g10 + b1.x, 0.f), fn11 = fmaxf(g11 + b1.y, 0.f);
                    float d0 = y00-fn00, d1 = y01-fn01, d2 = y10-fn10, d3 = y11-fn11;
                    sn = fmaf(d0,d0,sn); sn = fmaf(d1,d1,sn);
                    sn = fmaf(d2,d2,sn); sn = fmaf(d3,d3,sn);
                    sd = fmaf(y00,y00,sd); sd = fmaf(y01,y01,sd);
                    sd = fmaf(y10,y10,sd); sd = fmaf(y11,y11,sd);
                    float xn00 = fmaxf(0.5f*(y00 + g00 + b0.x), 0.f);
                    float xn01 = fmaxf(0.5f*(y01 + g01 + b0.y), 0.f);
                    float xn10 = fmaxf(0.5f*(y10 + g10 + b1.x), 0.f);
                    float xn11 = fmaxf(0.5f*(y11 + g11 + b1.y), 0.f);
                    int xi0 = gi0 >> 1, xi1 = gi1 >> 1;
                    float2 xv0 = sunpack(xs[xi0]);
                    float2 xv1 = sunpack(xs[xi1]);
                    float yn00 = xn00 + beta*(xn00 - xv0.x);
                    float yn01 = xn01 + beta*(xn01 - xv0.y);
                    float yn10 = xn10 + beta*(xn10 - xv1.x);
                    float yn11 = xn11 + beta*(xn11 - xv1.y);
                    float r0, r1, r2, r3;
                    uint32_t xh0 = split_hi(xn00, xn01, r0, r1);
                    xsw[xi0] = make_uint2(xh0, pack_lo(r0, r1));
                    uint32_t xh1 = split_hi(xn10, xn11, r2, r3);
                    xsw[xi1] = make_uint2(xh1, pack_lo(r2, r3));
                    uint32_t yh0 = split_hi(yn00, yn01, r0, r1);
                    uint32_t yh1 = split_hi(yn10, yn11, r2, r3);
                    yfw[yidx] = make_uint4(yh0, yh1, pack_lo(r0, r1), pack_lo(r2, r3));
                }
            }
        }

        // ---- deterministic CTA reduction: shfl within warp, then warp 0 ----
#pragma unroll
        for (int off = 16; off > 0; off >>= 1) {
            sn += __shfl_xor_sync(0xFFFFFFFFu, sn, off);
            sd += __shfl_xor_sync(0xFFFFFFFFu, sd, off);
        }
        if (lane == 0) { redsm[wid*2] = sn; redsm[wid*2 + 1] = sd; }
        __syncthreads();
        if (tid == 0) {
            float a = 0.f, b = 0.f;
#pragma unroll
            for (int w = 0; w < 8; ++w) { a += redsm[2*w]; b += redsm[2*w + 1]; }
            g_part[pass & 1][cta*2    ] = a;
            g_part[pass & 1][cta*2 + 1] = b;
        }

        // ---- grid barrier ----
        __syncthreads();
        if (tid == 0) {
            __threadfence();
            int gen = g_barg;
            if (atomicAdd(&g_barc, 1) == PCTAS - 1) {
                g_barc = 0;
                __threadfence();
                g_barg = gen + 1;
            } else {
                while (g_barg == gen) { }
                __threadfence();
            }
        }
        __syncthreads();

        // ---- redundant (identical on every CTA) err computation ----
        if (wid == 0) {
            const float* P = g_part[pass & 1];
            float a = 0.f, b = 0.f;
            for (int k = lane; k < PCTAS; k += 32) {
                a += P[2*k];
                b += P[2*k + 1];
            }
#pragma unroll
            for (int off = 16; off > 0; off >>= 1) {
                a += __shfl_xor_sync(0xFFFFFFFFu, a, off);
                b += __shfl_xor_sync(0xFFFFFFFFu, b, off);
            }
            if (lane == 0)
                errsm = sqrtf(a) / (1e-6f + sqrtf(b));
        }
        __syncthreads();
        float err = errsm;
        __syncthreads();
        if (!(err > 1e-4f)) { zpar = par; break; }
        par ^= 1;
    }
    if (zpar < 0) zpar = 0;    // never converged: y40 lives in buffer 0

    // ---- final output: out = relu(z @ W + b), z = g_yf[zpar] ----
    const uint4* __restrict__ yf = g_yf[zpar];
#pragma unroll 1
    for (int u = 0; u < 4; ++u) {
        const int mb  = jb*4 + u;
        const int mt0 = mb*8 + wm*2;
        float acc[2][4][4];
#pragma unroll
        for (int mi = 0; mi < 2; ++mi)
#pragma unroll
            for (int ni = 0; ni < 4; ++ni)
#pragma unroll
                for (int q = 0; q < 4; ++q) acc[mi][ni][q] = 0.f;
#pragma unroll
        for (int kk = 0; kk < 16; ++kk) {
            uint32_t ah[2][4], al[2][4];
#pragma unroll
            for (int mi = 0; mi < 2; ++mi) {
                int base = (((mt0 + mi)*16 + kk)*2)*32 + lane;
                uint4 u0 = yf[base];
                uint4 u1 = yf[base + 32];
                ah[mi][0] = u0.x; ah[mi][1] = u0.y;
                ah[mi][2] = u1.x; ah[mi][3] = u1.y;
                al[mi][0] = u0.z; al[mi][1] = u0.w;
                al[mi][2] = u1.z; al[mi][3] = u1.w;
            }
#pragma unroll
            for (int ni = 0; ni < 4; ++ni) {
                uint4 w = ws[(kk*8 + wn*4 + ni)*32 + lane];
                uint32_t bh[2] = {w.x, w.y};
                uint32_t bl[2] = {w.z, w.w};
#pragma unroll
                for (int mi = 0; mi < 2; ++mi) {
                    float* c = acc[mi][ni];
                    mma_bf16(c, ah[mi], bh);
                    mma_bf16(c, al[mi], bh);
                    mma_bf16(c, ah[mi], bl);
                }
            }
        }
#pragma unroll
        for (int mi = 0; mi < 2; ++mi) {
            int row0 = mb*128 + wm*32 + mi*16 + g;
#pragma unroll
            for (int ni = 0; ni < 4; ++ni) {
                int k8  = nb*8 + wn*4 + ni;
                int col = k8*8 + t2*2;
                int gi0 = row0*DIM + col, gi1 = gi0 + 8*DIM;
                float2 b0 = sunpack(g_bs[gi0 >> 1]);
                float2 b1 = sunpack(g_bs[gi1 >> 1]);
                *(float2*)(outp + gi0) = make_float2(
                    fmaxf(acc[mi][ni][0] + b0.x, 0.f),
                    fmaxf(acc[mi][ni][1] + b0.y, 0.f));
                *(float2*)(outp + gi1) = make_float2(
                    fmaxf(acc[mi][ni][2] + b1.x, 0.f),
                    fmaxf(acc[mi][ni][3] + b1.y, 0.f));
            }
        }
    }
}

// ---------------- launch ----------------
extern "C" void kernel_launch(void* const* d_in, const int* in_sizes, int n_in,
                              void* d_out, int out_size) {
    const float* x  = (const float*)d_in[0];
    const float* U  = (const float*)d_in[1];
    const float* ub = (const float*)d_in[2];
    const float* A  = (const float*)d_in[3];
    const float* B  = (const float*)d_in[4];
    (void)in_sizes; (void)n_in; (void)out_size;

    static int attr_done = 0;
    if (!attr_done) {
        cudaFuncSetAttribute(bias_tensor,
                             cudaFuncAttributeMaxDynamicSharedMemorySize, WS_BYTES);
        cudaFuncSetAttribute(persist_kernel,
                             cudaFuncAttributeMaxDynamicSharedMemorySize, WS_BYTES);
        attr_done = 1;
    }

    prep_kernel<<<DIM, DIM>>>(U, A, B);
    dim3 p2grid(16, 32);
    prep2_kernel<<<p2grid, 32>>>();
    flags_kernel<<<1, 32>>>();

    packx_kernel<<<YF_ELEMS/256, 256>>>(x);        // x -> A-frags in g_yf[0]
    dim3 bgrid(4, 256);
    bias_tensor<<<bgrid, 256, WS_BYTES>>>(ub);     // b = x@U^T + ub (split store)
    start_kernel<<<YF_ELEMS/256, 256>>>();         // body 1: y1 = x1 = relu(b/2)

    dim3 pgrid(4, 64);                             // 256 CTAs, co-resident
    persist_kernel<<<pgrid, 256, WS_BYTES>>>((float*)d_out);
}

// round 16
// speedup vs baseline: 1.2123x; 1.2123x over previous
#include <cuda_runtime.h>
#include <cuda_bf16.h>
#include <math.h>
#include <stdint.h>

#define BATCH    32768
#define DIM      256
#define MAX_IT   40
#define NTILES   1024              // 256 mb x 4 nb
#define SCTAS    444               // stealing grid (4, 111)
#define YF_ELEMS (2048*16*2*32)    // [mtile][kk16][half][lane] uint4
#define XS_ELEMS (BATCH*128)       // [row*128 + col/2] uint2
#define WS_BYTES 65536             // 4096 uint4: [kk][n8l][lane]

// ---------------- device scratch ----------------
__device__ uint4 g_yf[2][YF_ELEMS];     // y as A-fragments (hi,hi,lo,lo), ping-pong
__device__ uint2 g_xs[2][XS_ELEMS];     // x as interleaved bf16 splits, ping-pong
__device__ uint2 g_bs[XS_ELEMS];        // b as interleaved bf16 splits
__device__ uint4 g_wf[16*32*32];        // W as B-fragments [kk][n8][lane]
__device__ uint4 g_uf[16*32*32];        // U^T as B-fragments
__device__ __nv_bfloat16 g_w0[DIM*DIM];
__device__ __nv_bfloat16 g_w1[DIM*DIM];
__device__ __nv_bfloat16 g_u0[DIM*DIM];
__device__ __nv_bfloat16 g_u1[DIM*DIM];
__device__ float g_partial[NTILES*2];   // per-TILE partials (deterministic)
__device__ int   g_mctr[MAX_IT+1][4];   // work-steal counters per (it, nb)
__device__ int   g_ctr[MAX_IT+2];       // CTA arrival counters
__device__ int   g_active;
__device__ int   g_zpar;

// ---------------- helpers ----------------
__device__ __forceinline__ uint32_t bpack(__nv_bfloat16 a, __nv_bfloat16 b) {
    uint16_t ua = *(uint16_t*)&a, ub = *(uint16_t*)&b;
    return (uint32_t)ua | ((uint32_t)ub << 16);
}
__device__ __forceinline__ float2 bunpack(uint32_t u) {
    __nv_bfloat162 h = *(__nv_bfloat162*)&u;
    return make_float2(__bfloat162float(h.x), __bfloat162float(h.y));
}
__device__ __forceinline__ float2 sunpack(uint2 u) {
    float2 h = bunpack(u.x), l = bunpack(u.y);
    return make_float2(h.x + l.x, h.y + l.y);
}
__device__ __forceinline__ uint32_t split_hi(float a, float b,
                                             float& ra, float& rb) {
    __nv_bfloat16 ha = __float2bfloat16(a), hb = __float2bfloat16(b);
    ra = a - __bfloat162float(ha);
    rb = b - __bfloat162float(hb);
    return bpack(ha, hb);
}
__device__ __forceinline__ uint32_t pack_lo(float ra, float rb) {
    return bpack(__float2bfloat16(ra), __float2bfloat16(rb));
}
__device__ __forceinline__ void mma_bf16(float* c, const uint32_t* a, const uint32_t* b) {
    asm volatile(
        "mma.sync.aligned.m16n8k16.row.col.f32.bf16.bf16.f32 "
        "{%0,%1,%2,%3}, {%4,%5,%6,%7}, {%8,%9}, {%0,%1,%2,%3};"
        : "+f"(c[0]), "+f"(c[1]), "+f"(c[2]), "+f"(c[3])
        : "r"(a[0]), "r"(a[1]), "r"(a[2]), "r"(a[3]), "r"(b[0]), "r"(b[1]));
}

// ---------------- prep: Weff and U^T -> bf16 splits ----------
__global__ void prep_kernel(const float* __restrict__ U,
                            const float* __restrict__ A,
                            const float* __restrict__ B) {
    int i = blockIdx.x;    // k
    int j = threadIdx.x;   // n
    float u = U[j*DIM + i];
    __nv_bfloat16 uh = __float2bfloat16(u);
    g_u0[i*DIM + j] = uh;
    g_u1[i*DIM + j] = __float2bfloat16(u - __bfloat162float(uh));
    float s = 0.f;
#pragma unroll 8
    for (int p = 0; p < DIM; ++p)
        s = fmaf(A[p*DIM + i], A[p*DIM + j], s);
    float w = -s + B[j*DIM + i] - B[i*DIM + j];
    if (i == j) w += 0.8f;                    // (1-m), m=0.2
    __nv_bfloat16 h0 = __float2bfloat16(w);
    g_w0[i*DIM + j] = h0;
    g_w1[i*DIM + j] = __float2bfloat16(w - __bfloat162float(h0));
}

// ---------------- prep2: pack W and U^T into B-fragment order ----------------
__global__ void prep2_kernel() {
    int kk = blockIdx.x, n8 = blockIdx.y, lane = threadIdx.x;
    int k0 = kk*16 + 2*(lane & 3);
    int n  = n8*8 + (lane >> 2);
    int o  = (kk*32 + n8)*32 + lane;
    uint4 u;
    u.x = bpack(g_w0[(k0    )*DIM + n], g_w0[(k0+1)*DIM + n]);
    u.y = bpack(g_w0[(k0 + 8)*DIM + n], g_w0[(k0+9)*DIM + n]);
    u.z = bpack(g_w1[(k0    )*DIM + n], g_w1[(k0+1)*DIM + n]);
    u.w = bpack(g_w1[(k0 + 8)*DIM + n], g_w1[(k0+9)*DIM + n]);
    g_wf[o] = u;
    u.x = bpack(g_u0[(k0    )*DIM + n], g_u0[(k0+1)*DIM + n]);
    u.y = bpack(g_u0[(k0 + 8)*DIM + n], g_u0[(k0+9)*DIM + n]);
    u.z = bpack(g_u1[(k0    )*DIM + n], g_u1[(k0+1)*DIM + n]);
    u.w = bpack(g_u1[(k0 + 8)*DIM + n], g_u1[(k0+9)*DIM + n]);
    g_uf[o] = u;
}

// ---------------- flags ----------------
__global__ void flags_kernel() {
    int i = blockIdx.x * blockDim.x + threadIdx.x;
    if (i == 0) { g_active = 1; g_zpar = 0; }
    if (i <= MAX_IT + 1) g_ctr[i] = 0;
    if (i < (MAX_IT + 1) * 4) ((int*)g_mctr)[i] = 0;
}

// ---------------- packx: input x -> A-fragments in g_yf[0] (scratch) --------
__global__ void packx_kernel(const float* __restrict__ xin) {
    int idx  = blockIdx.x * blockDim.x + threadIdx.x;
    int lane = idx & 31;
    int k8   = (idx >> 5) & 31;
    int mt   = idx >> 10;
    int row0 = mt*16 + (lane >> 2);
    int col  = k8*8 + (lane & 3)*2;
    int gi0  = row0*DIM + col, gi1 = gi0 + 8*DIM;
    float2 v0 = *(const float2*)(xin + gi0);
    float2 v1 = *(const float2*)(xin + gi1);
    float r0, r1, r2, r3;
    uint32_t h0 = split_hi(v0.x, v0.y, r0, r1);
    uint32_t h1 = split_hi(v1.x, v1.y, r2, r3);
    int yidx = ((mt*16 + (k8 >> 1))*2 + (k8 & 1))*32 + lane;
    g_yf[0][yidx] = make_uint4(h0, h1, pack_lo(r0, r1), pack_lo(r2, r3));
}

// ---------------- bias GEMM (tensor): b = x @ U^T + ub -> split storage ------
__global__ void __launch_bounds__(256, 3)
bias_tensor(const float* __restrict__ ub) {
    extern __shared__ __align__(16) uint4 ws[];
    const int tid  = threadIdx.x;
    const int lane = tid & 31;
    const int wid  = tid >> 5;
    const int wm   = wid & 3;
    const int wn   = wid >> 2;
    const int mb   = blockIdx.y;
    const int nb   = blockIdx.x;

#pragma unroll
    for (int j = 0; j < 16; ++j) {
        int linear = j*256 + tid;
        int l  = linear & 31;
        int r  = linear >> 5;
        int kk = r >> 3, n8l = r & 7;
        ws[linear] = g_uf[kk*1024 + (nb*8 + n8l)*32 + l];
    }
    __syncthreads();

    const uint4* __restrict__ yf = g_yf[0];
    float acc[2][4][4];
#pragma unroll
    for (int mi = 0; mi < 2; ++mi)
#pragma unroll
        for (int ni = 0; ni < 4; ++ni)
#pragma unroll
            for (int q = 0; q < 4; ++q) acc[mi][ni][q] = 0.f;
    const int mt0 = mb*8 + wm*2;
#pragma unroll
    for (int kk = 0; kk < 16; ++kk) {
        uint32_t ah[2][4], al[2][4];
#pragma unroll
        for (int mi = 0; mi < 2; ++mi) {
            int base = (((mt0 + mi)*16 + kk)*2)*32 + lane;
            uint4 u0 = yf[base];
            uint4 u1 = yf[base + 32];
            ah[mi][0] = u0.x; ah[mi][1] = u0.y; ah[mi][2] = u1.x; ah[mi][3] = u1.y;
            al[mi][0] = u0.z; al[mi][1] = u0.w; al[mi][2] = u1.z; al[mi][3] = u1.w;
        }
#pragma unroll
        for (int ni = 0; ni < 4; ++ni) {
            uint4 u = ws[(kk*8 + wn*4 + ni)*32 + lane];
            uint32_t bh[2] = {u.x, u.y};
            uint32_t bl[2] = {u.z, u.w};
#pragma unroll
            for (int mi = 0; mi < 2; ++mi) {
                float* c = acc[mi][ni];
                mma_bf16(c, ah[mi], bh);
                mma_bf16(c, al[mi], bh);
                mma_bf16(c, ah[mi], bl);
            }
        }
    }
    const int t2 = lane & 3, g = lane >> 2;
#pragma unroll
    for (int mi = 0; mi < 2; ++mi) {
        int row0 = mb*128 + wm*32 + mi*16 + g;
#pragma unroll
        for (int ni = 0; ni < 4; ++ni) {
            int k8  = nb*8 + wn*4 + ni;
            int col = k8*8 + t2*2;
            int gi0 = row0*DIM + col, gi1 = gi0 + 8*DIM;
            float2 u = *(const float2*)(ub + col);
            float b00 = acc[mi][ni][0] + u.x, b01 = acc[mi][ni][1] + u.y;
            float b10 = acc[mi][ni][2] + u.x, b11 = acc[mi][ni][3] + u.y;
            float r0, r1, r2, r3;
            uint32_t h0 = split_hi(b00, b01, r0, r1);
            g_bs[gi0 >> 1] = make_uint2(h0, pack_lo(r0, r1));
            uint32_t h1 = split_hi(b10, b11, r2, r3);
            g_bs[gi1 >> 1] = make_uint2(h1, pack_lo(r2, r3));
        }
    }
}

// ---------------- start: body 1 analytically (y0=x0=0, beta1=0) --------------
__global__ void start_kernel() {
    int idx  = blockIdx.x * blockDim.x + threadIdx.x;
    int lane = idx & 31;
    int k8   = (idx >> 5) & 31;
    int mt   = idx >> 10;
    int row0 = mt*16 + (lane >> 2);
    int col  = k8*8 + (lane & 3)*2;
    int gi0  = row0*DIM + col, gi1 = gi0 + 8*DIM;
    float2 b0 = sunpack(g_bs[gi0 >> 1]);
    float2 b1 = sunpack(g_bs[gi1 >> 1]);
    float v00 = fmaxf(0.5f*b0.x, 0.f), v01 = fmaxf(0.5f*b0.y, 0.f);
    float v10 = fmaxf(0.5f*b1.x, 0.f), v11 = fmaxf(0.5f*b1.y, 0.f);
    float r0, r1, r2, r3;
    uint32_t h0 = split_hi(v00, v01, r0, r1);
    uint32_t l0 = pack_lo(r0, r1);
    uint32_t h1 = split_hi(v10, v11, r2, r3);
    uint32_t l1 = pack_lo(r2, r3);
    int yidx = ((mt*16 + (k8 >> 1))*2 + (k8 & 1))*32 + lane;
    g_yf[1][yidx] = make_uint4(h0, h1, l0, l1);
    g_xs[1][gi0 >> 1] = make_uint2(h0, l0);
    g_xs[1][gi1 >> 1] = make_uint2(h1, l1);
}

// ---------------- iteration kernel (bodies 2..40), work-stealing ----------
__global__ void __launch_bounds__(256, 3)
iter_kernel(float beta, int par, int it) {
    if (g_active == 0) return;
    extern __shared__ __align__(16) uint4 ws[];
    __shared__ float redsm[16];
    __shared__ int mbs;
    const int tid  = threadIdx.x;
    const int lane = tid & 31;
    const int wid  = tid >> 5;
    const int wm   = wid & 3;
    const int wn   = wid >> 2;
    const int nb   = blockIdx.x;       // fixed N slice per CTA
    const int t2 = lane & 3, g = lane >> 2;

    // ---- stage W slice ONCE per kernel ----
#pragma unroll
    for (int j = 0; j < 16; ++j) {
        int linear = j*256 + tid;
        int l  = linear & 31;
        int r  = linear >> 5;
        int kk = r >> 3, n8l = r & 7;
        ws[linear] = g_wf[kk*1024 + (nb*8 + n8l)*32 + l];
    }

    const uint4* __restrict__ yf = g_yf[par];
    const uint2* __restrict__ xs = g_xs[par];
    uint2* __restrict__ xsw = g_xs[par ^ 1];
    uint4* __restrict__ yfw = g_yf[par ^ 1];

    for (;;) {
        __syncthreads();              // W ready / mbs consumed
        if (tid == 0) mbs = atomicAdd(&g_mctr[it][nb], 1);
        __syncthreads();
        const int mb = mbs;
        if (mb >= 256) break;
        const int mt0 = mb*8 + wm*2;

        float acc[2][4][4];
#pragma unroll
        for (int mi = 0; mi < 2; ++mi)
#pragma unroll
            for (int ni = 0; ni < 4; ++ni)
#pragma unroll
                for (int q = 0; q < 4; ++q) acc[mi][ni][q] = 0.f;
#pragma unroll
        for (int kk = 0; kk < 16; ++kk) {
            uint32_t ah[2][4], al[2][4];
#pragma unroll
            for (int mi = 0; mi < 2; ++mi) {
                int base = (((mt0 + mi)*16 + kk)*2)*32 + lane;
                uint4 u0 = yf[base];
                uint4 u1 = yf[base + 32];
                ah[mi][0] = u0.x; ah[mi][1] = u0.y;
                ah[mi][2] = u1.x; ah[mi][3] = u1.y;
                al[mi][0] = u0.z; al[mi][1] = u0.w;
                al[mi][2] = u1.z; al[mi][3] = u1.w;
            }
#pragma unroll
            for (int ni = 0; ni < 4; ++ni) {
                uint4 w = ws[(kk*8 + wn*4 + ni)*32 + lane];
                uint32_t bh[2] = {w.x, w.y};
                uint32_t bl[2] = {w.z, w.w};
#pragma unroll
                for (int mi = 0; mi < 2; ++mi) {
                    float* c = acc[mi][ni];
                    mma_bf16(c, ah[mi], bh);
                    mma_bf16(c, al[mi], bh);
                    mma_bf16(c, ah[mi], bl);
                }
            }
        }

        float sn = 0.f, sd = 0.f;
#pragma unroll
        for (int mi = 0; mi < 2; ++mi) {
            int row0 = mb*128 + wm*32 + mi*16 + g;
#pragma unroll
            for (int ni = 0; ni < 4; ++ni) {
                int k8  = nb*8 + wn*4 + ni;
                int col = k8*8 + t2*2;
                int yidx = (((mt0 + mi)*16 + (k8 >> 1))*2 + (k8 & 1))*32 + lane;
                uint4 yu = yf[yidx];
                float2 a0h = bunpack(yu.x), a1h = bunpack(yu.y);
                float2 a0l = bunpack(yu.z), a1l = bunpack(yu.w);
                float y00 = a0h.x + a0l.x, y01 = a0h.y + a0l.y;
                float y10 = a1h.x + a1l.x, y11 = a1h.y + a1l.y;
                float g00 = acc[mi][ni][0], g01 = acc[mi][ni][1];
                float g10 = acc[mi][ni][2], g11 = acc[mi][ni][3];
                int gi0 = row0*DIM + col, gi1 = gi0 + 8*DIM;
                float2 b0 = sunpack(g_bs[gi0 >> 1]);
                float2 b1 = sunpack(g_bs[gi1 >> 1]);
                float fn00 = fmaxf(g00 + b0.x, 0.f), fn01 = fmaxf(g01 + b0.y, 0.f);
                float fn10 = fmaxf(g10 + b1.x, 0.f), fn11 = fmaxf(g11 + b1.y, 0.f);
                float d0 = y00-fn00, d1 = y01-fn01, d2 = y10-fn10, d3 = y11-fn11;
                sn = fmaf(d0,d0,sn); sn = fmaf(d1,d1,sn);
                sn = fmaf(d2,d2,sn); sn = fmaf(d3,d3,sn);
                sd = fmaf(y00,y00,sd); sd = fmaf(y01,y01,sd);
                sd = fmaf(y10,y10,sd); sd = fmaf(y11,y11,sd);
                float xn00 = fmaxf(0.5f*(y00 + g00 + b0.x), 0.f);
                float xn01 = fmaxf(0.5f*(y01 + g01 + b0.y), 0.f);
                float xn10 = fmaxf(0.5f*(y10 + g10 + b1.x), 0.f);
                float xn11 = fmaxf(0.5f*(y11 + g11 + b1.y), 0.f);
                int xi0 = gi0 >> 1, xi1 = gi1 >> 1;
                float2 xv0 = sunpack(xs[xi0]);
                float2 xv1 = sunpack(xs[xi1]);
                float yn00 = xn00 + beta*(xn00 - xv0.x);
                float yn01 = xn01 + beta*(xn01 - xv0.y);
                float yn10 = xn10 + beta*(xn10 - xv1.x);
                float yn11 = xn11 + beta*(xn11 - xv1.y);
                float r0, r1, r2, r3;
                uint32_t xh0 = split_hi(xn00, xn01, r0, r1);
                xsw[xi0] = make_uint2(xh0, pack_lo(r0, r1));
                uint32_t xh1 = split_hi(xn10, xn11, r2, r3);
                xsw[xi1] = make_uint2(xh1, pack_lo(r2, r3));
                uint32_t yh0 = split_hi(yn00, yn01, r0, r1);
                uint32_t yh1 = split_hi(yn10, yn11, r2, r3);
                yfw[yidx] = make_uint4(yh0, yh1, pack_lo(r0, r1), pack_lo(r2, r3));
            }
        }

        // ---- per-tile deterministic reduction ----
#pragma unroll
        for (int off = 16; off > 0; off >>= 1) {
            sn += __shfl_xor_sync(0xFFFFFFFFu, sn, off);
            sd += __shfl_xor_sync(0xFFFFFFFFu, sd, off);
        }
        if (lane == 0) { redsm[wid*2] = sn; redsm[wid*2 + 1] = sd; }
        __syncthreads();
        if (tid == 0) {
            float a = 0.f, b = 0.f;
#pragma unroll
            for (int w = 0; w < 8; ++w) { a += redsm[2*w]; b += redsm[2*w + 1]; }
            int tile = mb*4 + nb;
            g_partial[tile*2    ] = a;
            g_partial[tile*2 + 1] = b;
        }
    }

    // ---- merged convergence check: last-arriving CTA reduces and gates ----
    __shared__ int islast;
    __threadfence();
    if (tid == 0) islast = (atomicAdd(&g_ctr[it], 1) == SCTAS - 1);
    __syncthreads();
    if (islast) {
        float a = 0.f, b = 0.f;
#pragma unroll
        for (int k = 0; k < 4; ++k) {
            a += g_partial[2*(tid + k*256)    ];
            b += g_partial[2*(tid + k*256) + 1];
        }
        float* red = redsm;        // reuse small smem? need 512 floats -> use ws
        red = (float*)ws;
        red[tid] = a; red[256 + tid] = b;
        __syncthreads();
#pragma unroll
        for (int s = 128; s > 0; s >>= 1) {
            if (tid < s) { red[tid] += red[tid + s]; red[256 + tid] += red[256 + tid + s]; }
            __syncthreads();
        }
        if (tid == 0) {
            float err = sqrtf(red[0]) / (1e-6f + sqrtf(red[256]));
            if (!(err > 1e-4f)) {
                g_active = 0;
                g_zpar = par;
            }
        }
    }
}

// ---------------- final kernel: out = relu(z @ W + b), z = g_yf[g_zpar] ------
__global__ void __launch_bounds__(256, 3)
final_kernel(float* __restrict__ outp) {
    extern __shared__ __align__(16) uint4 ws[];
    const int tid  = threadIdx.x;
    const int lane = tid & 31;
    const int wid  = tid >> 5;
    const int wm   = wid & 3;
    const int wn   = wid >> 2;
    const int mb   = blockIdx.y;
    const int nb   = blockIdx.x;
    const int par  = g_zpar;

#pragma unroll
    for (int j = 0; j < 16; ++j) {
        int linear = j*256 + tid;
        int l  = linear & 31;
        int r  = linear >> 5;
        int kk = r >> 3, n8l = r & 7;
        ws[linear] = g_wf[kk*1024 + (nb*8 + n8l)*32 + l];
    }
    __syncthreads();

    const uint4* __restrict__ yf = g_yf[par];
    float acc[2][4][4];
#pragma unroll
    for (int mi = 0; mi < 2; ++mi)
#pragma unroll
        for (int ni = 0; ni < 4; ++ni)
#pragma unroll
            for (int q = 0; q < 4; ++q) acc[mi][ni][q] = 0.f;
    const int mt0 = mb*8 + wm*2;
#pragma unroll
    for (int kk = 0; kk < 16; ++kk) {
        uint32_t ah[2][4], al[2][4];
#pragma unroll
        for (int mi = 0; mi < 2; ++mi) {
            int base = (((mt0 + mi)*16 + kk)*2)*32 + lane;
            uint4 u0 = yf[base];
            uint4 u1 = yf[base + 32];
            ah[mi][0] = u0.x; ah[mi][1] = u0.y; ah[mi][2] = u1.x; ah[mi][3] = u1.y;
            al[mi][0] = u0.z; al[mi][1] = u0.w; al[mi][2] = u1.z; al[mi][3] = u1.w;
        }
#pragma unroll
        for (int ni = 0; ni < 4; ++ni) {
            uint4 u = ws[(kk*8 + wn*4 + ni)*32 + lane];
            uint32_t bh[2] = {u.x, u.y};
            uint32_t bl[2] = {u.z, u.w};
#pragma unroll
            for (int mi = 0; mi < 2; ++mi) {
                float* c = acc[mi][ni];
                mma_bf16(c, ah[mi], bh);
                mma_bf16(c, al[mi], bh);
                mma_bf16(c, ah[mi], bl);
            }
        }
    }
    const int t2 = lane & 3, g = lane >> 2;
#pragma unroll
    for (int mi = 0; mi < 2; ++mi) {
        int row0 = mb*128 + wm*32 + mi*16 + g;
#pragma unroll
        for (int ni = 0; ni < 4; ++ni) {
            int k8  = nb*8 + wn*4 + ni;
            int col = k8*8 + t2*2;
            int gi0 = row0*DIM + col, gi1 = gi0 + 8*DIM;
            float2 b0 = sunpack(g_bs[gi0 >> 1]);
            float2 b1 = sunpack(g_bs[gi1 >> 1]);
            *(float2*)(outp + gi0) = make_float2(
                fmaxf(acc[mi][ni][0] + b0.x, 0.f),
                fmaxf(acc[mi][ni][1] + b0.y, 0.f));
            *(float2*)(outp + gi1) = make_float2(
                fmaxf(acc[mi][ni][2] + b1.x, 0.f),
                fmaxf(acc[mi][ni][3] + b1.y, 0.f));
        }
    }
}

// ---------------- launch ----------------
extern "C" void kernel_launch(void* const* d_in, const int* in_sizes, int n_in,
                              void* d_out, int out_size) {
    const float* x  = (const float*)d_in[0];
    const float* U  = (const float*)d_in[1];
    const float* ub = (const float*)d_in[2];
    const float* A  = (const float*)d_in[3];
    const float* B  = (const float*)d_in[4];
    (void)in_sizes; (void)n_in; (void)out_size;

    static int attr_done = 0;
    if (!attr_done) {
        cudaFuncSetAttribute(bias_tensor,
                             cudaFuncAttributeMaxDynamicSharedMemorySize, WS_BYTES);
        cudaFuncSetAttribute(iter_kernel,
                             cudaFuncAttributeMaxDynamicSharedMemorySize, WS_BYTES);
        cudaFuncSetAttribute(final_kernel,
                             cudaFuncAttributeMaxDynamicSharedMemorySize, WS_BYTES);
        attr_done = 1;
    }

    prep_kernel<<<DIM, DIM>>>(U, A, B);
    dim3 p2grid(16, 32);
    prep2_kernel<<<p2grid, 32>>>();
    flags_kernel<<<1, 256>>>();

    packx_kernel<<<YF_ELEMS/256, 256>>>(x);
    dim3 bgrid(4, 256);
    bias_tensor<<<bgrid, 256, WS_BYTES>>>(ub);
    start_kernel<<<YF_ELEMS/256, 256>>>();      // body 1: y1 = x1 = relu(b/2)

    dim3 igrid(4, 111);                         // 444 stealing CTAs
    float t = 1.6180339887f;                    // t1
    for (int i = 2; i <= MAX_IT; ++i) {
        float tn   = 0.5f * (1.0f + sqrtf(1.0f + 4.0f * t * t));
        float beta = (t - 1.0f) / tn;
        iter_kernel<<<igrid, 256, WS_BYTES>>>(beta, (i - 1) & 1, i - 1);
        t = tn;
    }
    dim3 fgrid(4, 256);
    final_kernel<<<fgrid, 256, WS_BYTES>>>((float*)d_out);
}

// round 17
// speedup vs baseline: 1.3084x; 1.0793x over previous
#include <cuda_runtime.h>
#include <cuda_bf16.h>
#include <math.h>
#include <stdint.h>

#define BATCH    32768
#define DIM      256
#define MAX_IT   40
#define NCTAS    1024              // grid (4, 256)
#define YF_ELEMS (2048*16*2*32)    // [mtile][kk16][half][lane] uint4
#define WS_BYTES 65536             // 4096 uint4: [kk][n8l][lane]

// ---------------- device scratch ----------------
__device__ uint4 g_yf[2][YF_ELEMS];     // y as A-fragments (hi,hi,lo,lo), ping-pong
__device__ uint4 g_xf[2][YF_ELEMS];     // x in identical fragment layout
__device__ uint4 g_bf[YF_ELEMS];        // b in identical fragment layout
__device__ uint4 g_wf[16*32*32];        // W as B-fragments [kk][n8][lane]
__device__ uint4 g_uf[16*32*32];        // U^T as B-fragments
__device__ __nv_bfloat16 g_w0[DIM*DIM];
__device__ __nv_bfloat16 g_w1[DIM*DIM];
__device__ __nv_bfloat16 g_u0[DIM*DIM];
__device__ __nv_bfloat16 g_u1[DIM*DIM];
__device__ float g_partial[NCTAS*2];
__device__ int   g_ctr[MAX_IT+2];
__device__ int   g_active;
__device__ int   g_zpar;

// ---------------- helpers ----------------
__device__ __forceinline__ uint32_t bpack(__nv_bfloat16 a, __nv_bfloat16 b) {
    uint16_t ua = *(uint16_t*)&a, ub = *(uint16_t*)&b;
    return (uint32_t)ua | ((uint32_t)ub << 16);
}
__device__ __forceinline__ float2 bunpack(uint32_t u) {
    __nv_bfloat162 h = *(__nv_bfloat162*)&u;
    return make_float2(__bfloat162float(h.x), __bfloat162float(h.y));
}
__device__ __forceinline__ uint32_t split_hi(float a, float b,
                                             float& ra, float& rb) {
    __nv_bfloat16 ha = __float2bfloat16(a), hb = __float2bfloat16(b);
    ra = a - __bfloat162float(ha);
    rb = b - __bfloat162float(hb);
    return bpack(ha, hb);
}
__device__ __forceinline__ uint32_t pack_lo(float ra, float rb) {
    return bpack(__float2bfloat16(ra), __float2bfloat16(rb));
}
// unpack a fragment uint4 (hi0,hi1,lo0,lo1) -> 4 fp32 values
__device__ __forceinline__ void funpack(uint4 u, float& v00, float& v01,
                                        float& v10, float& v11) {
    float2 h0 = bunpack(u.x), h1 = bunpack(u.y);
    float2 l0 = bunpack(u.z), l1 = bunpack(u.w);
    v00 = h0.x + l0.x;  v01 = h0.y + l0.y;
    v10 = h1.x + l1.x;  v11 = h1.y + l1.y;
}
__device__ __forceinline__ void mma_bf16(float* c, const uint32_t* a, const uint32_t* b) {
    asm volatile(
        "mma.sync.aligned.m16n8k16.row.col.f32.bf16.bf16.f32 "
        "{%0,%1,%2,%3}, {%4,%5,%6,%7}, {%8,%9}, {%0,%1,%2,%3};"
        : "+f"(c[0]), "+f"(c[1]), "+f"(c[2]), "+f"(c[3])
        : "r"(a[0]), "r"(a[1]), "r"(a[2]), "r"(a[3]), "r"(b[0]), "r"(b[1]));
}

// ---------------- prep: Weff and U^T -> bf16 splits ----------
__global__ void prep_kernel(const float* __restrict__ U,
                            const float* __restrict__ A,
                            const float* __restrict__ B) {
    int i = blockIdx.x;    // k
    int j = threadIdx.x;   // n
    float u = U[j*DIM + i];
    __nv_bfloat16 uh = __float2bfloat16(u);
    g_u0[i*DIM + j] = uh;
    g_u1[i*DIM + j] = __float2bfloat16(u - __bfloat162float(uh));
    float s = 0.f;
#pragma unroll 8
    for (int p = 0; p < DIM; ++p)
        s = fmaf(A[p*DIM + i], A[p*DIM + j], s);
    float w = -s + B[j*DIM + i] - B[i*DIM + j];
    if (i == j) w += 0.8f;                    // (1-m), m=0.2
    __nv_bfloat16 h0 = __float2bfloat16(w);
    g_w0[i*DIM + j] = h0;
    g_w1[i*DIM + j] = __float2bfloat16(w - __bfloat162float(h0));
}

// ---------------- prep2: pack W and U^T into B-fragment order ----------------
__global__ void prep2_kernel() {
    int kk = blockIdx.x, n8 = blockIdx.y, lane = threadIdx.x;
    int k0 = kk*16 + 2*(lane & 3);
    int n  = n8*8 + (lane >> 2);
    int o  = (kk*32 + n8)*32 + lane;
    uint4 u;
    u.x = bpack(g_w0[(k0    )*DIM + n], g_w0[(k0+1)*DIM + n]);
    u.y = bpack(g_w0[(k0 + 8)*DIM + n], g_w0[(k0+9)*DIM + n]);
    u.z = bpack(g_w1[(k0    )*DIM + n], g_w1[(k0+1)*DIM + n]);
    u.w = bpack(g_w1[(k0 + 8)*DIM + n], g_w1[(k0+9)*DIM + n]);
    g_wf[o] = u;
    u.x = bpack(g_u0[(k0    )*DIM + n], g_u0[(k0+1)*DIM + n]);
    u.y = bpack(g_u0[(k0 + 8)*DIM + n], g_u0[(k0+9)*DIM + n]);
    u.z = bpack(g_u1[(k0    )*DIM + n], g_u1[(k0+1)*DIM + n]);
    u.w = bpack(g_u1[(k0 + 8)*DIM + n], g_u1[(k0+9)*DIM + n]);
    g_uf[o] = u;
}

// ---------------- flags ----------------
__global__ void flags_kernel() {
    int i = threadIdx.x;
    if (i == 0) { g_active = 1; g_zpar = 0; }
    if (i <= MAX_IT + 1) g_ctr[i] = 0;
}

// ---------------- packx: input x -> A-fragments in g_yf[0] (scratch) --------
__global__ void packx_kernel(const float* __restrict__ xin) {
    int idx  = blockIdx.x * blockDim.x + threadIdx.x;
    int lane = idx & 31;
    int k8   = (idx >> 5) & 31;
    int mt   = idx >> 10;
    int row0 = mt*16 + (lane >> 2);
    int col  = k8*8 + (lane & 3)*2;
    int gi0  = row0*DIM + col, gi1 = gi0 + 8*DIM;
    float2 v0 = *(const float2*)(xin + gi0);
    float2 v1 = *(const float2*)(xin + gi1);
    float r0, r1, r2, r3;
    uint32_t h0 = split_hi(v0.x, v0.y, r0, r1);
    uint32_t h1 = split_hi(v1.x, v1.y, r2, r3);
    int yidx = ((mt*16 + (k8 >> 1))*2 + (k8 & 1))*32 + lane;
    g_yf[0][yidx] = make_uint4(h0, h1, pack_lo(r0, r1), pack_lo(r2, r3));
}

// ---------------- bias GEMM (tensor): b = x @ U^T + ub -> fragment storage ---
__global__ void __launch_bounds__(256, 3)
bias_tensor(const float* __restrict__ ub) {
    extern __shared__ __align__(16) uint4 ws[];
    const int tid  = threadIdx.x;
    const int lane = tid & 31;
    const int wid  = tid >> 5;
    const int wm   = wid & 3;
    const int wn   = wid >> 2;
    const int mb   = blockIdx.y;
    const int nb   = blockIdx.x;

#pragma unroll
    for (int j = 0; j < 16; ++j) {
        int linear = j*256 + tid;
        int l  = linear & 31;
        int r  = linear >> 5;
        int kk = r >> 3, n8l = r & 7;
        ws[linear] = g_uf[kk*1024 + (nb*8 + n8l)*32 + l];
    }
    __syncthreads();

    const uint4* __restrict__ yf = g_yf[0];
    float acc[2][4][4];
#pragma unroll
    for (int mi = 0; mi < 2; ++mi)
#pragma unroll
        for (int ni = 0; ni < 4; ++ni)
#pragma unroll
            for (int q = 0; q < 4; ++q) acc[mi][ni][q] = 0.f;
    const int mt0 = mb*8 + wm*2;
#pragma unroll
    for (int kk = 0; kk < 16; ++kk) {
        uint32_t ah[2][4], al[2][4];
#pragma unroll
        for (int mi = 0; mi < 2; ++mi) {
            int base = (((mt0 + mi)*16 + kk)*2)*32 + lane;
            uint4 u0 = yf[base];
            uint4 u1 = yf[base + 32];
            ah[mi][0] = u0.x; ah[mi][1] = u0.y; ah[mi][2] = u1.x; ah[mi][3] = u1.y;
            al[mi][0] = u0.z; al[mi][1] = u0.w; al[mi][2] = u1.z; al[mi][3] = u1.w;
        }
#pragma unroll
        for (int ni = 0; ni < 4; ++ni) {
            uint4 u = ws[(kk*8 + wn*4 + ni)*32 + lane];
            uint32_t bh[2] = {u.x, u.y};
            uint32_t bl[2] = {u.z, u.w};
#pragma unroll
            for (int mi = 0; mi < 2; ++mi) {
                float* c = acc[mi][ni];
                mma_bf16(c, ah[mi], bh);
                mma_bf16(c, al[mi], bh);
                mma_bf16(c, ah[mi], bl);
            }
        }
    }
    const int t2 = lane & 3;
#pragma unroll
    for (int mi = 0; mi < 2; ++mi) {
#pragma unroll
        for (int ni = 0; ni < 4; ++ni) {
            int k8  = nb*8 + wn*4 + ni;
            int col = k8*8 + t2*2;
            int yidx = (((mt0 + mi)*16 + (k8 >> 1))*2 + (k8 & 1))*32 + lane;
            float2 u = *(const float2*)(ub + col);
            float b00 = acc[mi][ni][0] + u.x, b01 = acc[mi][ni][1] + u.y;
            float b10 = acc[mi][ni][2] + u.x, b11 = acc[mi][ni][3] + u.y;
            float r0, r1, r2, r3;
            uint32_t h0 = split_hi(b00, b01, r0, r1);
            uint32_t h1 = split_hi(b10, b11, r2, r3);
            g_bf[yidx] = make_uint4(h0, h1, pack_lo(r0, r1), pack_lo(r2, r3));
        }
    }
}

// ---------------- start: body 1 analytically (y0=x0=0, beta1=0) --------------
// x1 = y1 = relu(b/2); fragment layout throughout.
__global__ void start_kernel() {
    int yidx = blockIdx.x * blockDim.x + threadIdx.x;
    uint4 bu = g_bf[yidx];
    float b00, b01, b10, b11;
    funpack(bu, b00, b01, b10, b11);
    float v00 = fmaxf(0.5f*b00, 0.f), v01 = fmaxf(0.5f*b01, 0.f);
    float v10 = fmaxf(0.5f*b10, 0.f), v11 = fmaxf(0.5f*b11, 0.f);
    float r0, r1, r2, r3;
    uint32_t h0 = split_hi(v00, v01, r0, r1);
    uint32_t l0 = pack_lo(r0, r1);
    uint32_t h1 = split_hi(v10, v11, r2, r3);
    uint32_t l1 = pack_lo(r2, r3);
    uint4 o = make_uint4(h0, h1, l0, l1);
    g_yf[1][yidx] = o;
    g_xf[1][yidx] = o;
}

// ---------------- iteration kernel (bodies 2..40) ----------
__global__ void __launch_bounds__(256, 3)
iter_kernel(float beta, int par, int it) {
    if (g_active == 0) return;
    extern __shared__ __align__(16) uint4 ws[];
    const int tid  = threadIdx.x;
    const int lane = tid & 31;
    const int wid  = tid >> 5;
    const int wm   = wid & 3;
    const int wn   = wid >> 2;
    const int mb   = blockIdx.y;
    const int nb   = blockIdx.x;

#pragma unroll
    for (int j = 0; j < 16; ++j) {
        int linear = j*256 + tid;
        int l  = linear & 31;
        int r  = linear >> 5;
        int kk = r >> 3, n8l = r & 7;
        ws[linear] = g_wf[kk*1024 + (nb*8 + n8l)*32 + l];
    }
    __syncthreads();

    const uint4* __restrict__ yf = g_yf[par];

    float acc[2][4][4];
#pragma unroll
    for (int mi = 0; mi < 2; ++mi)
#pragma unroll
        for (int ni = 0; ni < 4; ++ni)
#pragma unroll
            for (int q = 0; q < 4; ++q) acc[mi][ni][q] = 0.f;

    const int mt0 = mb*8 + wm*2;

#pragma unroll
    for (int kk = 0; kk < 16; ++kk) {
        uint32_t ah[2][4], al[2][4];
#pragma unroll
        for (int mi = 0; mi < 2; ++mi) {
            int base = (((mt0 + mi)*16 + kk)*2)*32 + lane;
            uint4 u0 = yf[base];
            uint4 u1 = yf[base + 32];
            ah[mi][0] = u0.x; ah[mi][1] = u0.y; ah[mi][2] = u1.x; ah[mi][3] = u1.y;
            al[mi][0] = u0.z; al[mi][1] = u0.w; al[mi][2] = u1.z; al[mi][3] = u1.w;
        }
#pragma unroll
        for (int ni = 0; ni < 4; ++ni) {
            uint4 u = ws[(kk*8 + wn*4 + ni)*32 + lane];
            uint32_t bh[2] = {u.x, u.y};
            uint32_t bl[2] = {u.z, u.w};
#pragma unroll
            for (int mi = 0; mi < 2; ++mi) {
                float* c = acc[mi][ni];
                mma_bf16(c, ah[mi], bh);
                mma_bf16(c, al[mi], bh);
                mma_bf16(c, ah[mi], bl);
            }
        }
    }

    // ---- fused epilogue: everything in fragment layout ----
    const uint4* __restrict__ xf  = g_xf[par];
    uint4* __restrict__ xfw = g_xf[par ^ 1];
    uint4* __restrict__ yfw = g_yf[par ^ 1];
    float sn = 0.f, sd = 0.f;

#pragma unroll
    for (int mi = 0; mi < 2; ++mi) {
#pragma unroll
        for (int ni = 0; ni < 4; ++ni) {
            int k8   = nb*8 + wn*4 + ni;
            int yidx = (((mt0 + mi)*16 + (k8 >> 1))*2 + (k8 & 1))*32 + lane;
            float y00, y01, y10, y11;
            funpack(yf[yidx], y00, y01, y10, y11);
            float b00, b01, b10, b11;
            funpack(g_bf[yidx], b00, b01, b10, b11);
            float g00 = acc[mi][ni][0], g01 = acc[mi][ni][1];
            float g10 = acc[mi][ni][2], g11 = acc[mi][ni][3];
            float fn00 = fmaxf(g00 + b00, 0.f), fn01 = fmaxf(g01 + b01, 0.f);
            float fn10 = fmaxf(g10 + b10, 0.f), fn11 = fmaxf(g11 + b11, 0.f);
            float d0 = y00-fn00, d1 = y01-fn01, d2 = y10-fn10, d3 = y11-fn11;
            sn = fmaf(d0,d0,sn); sn = fmaf(d1,d1,sn);
            sn = fmaf(d2,d2,sn); sn = fmaf(d3,d3,sn);
            sd = fmaf(y00,y00,sd); sd = fmaf(y01,y01,sd);
            sd = fmaf(y10,y10,sd); sd = fmaf(y11,y11,sd);
            float xn00 = fmaxf(0.5f*(y00 + g00 + b00), 0.f);
            float xn01 = fmaxf(0.5f*(y01 + g01 + b01), 0.f);
            float xn10 = fmaxf(0.5f*(y10 + g10 + b10), 0.f);
            float xn11 = fmaxf(0.5f*(y11 + g11 + b11), 0.f);
            float xv00, xv01, xv10, xv11;
            funpack(xf[yidx], xv00, xv01, xv10, xv11);
            float yn00 = xn00 + beta*(xn00 - xv00);
            float yn01 = xn01 + beta*(xn01 - xv01);
            float yn10 = xn10 + beta*(xn10 - xv10);
            float yn11 = xn11 + beta*(xn11 - xv11);
            float r0, r1, r2, r3;
            uint32_t xh0 = split_hi(xn00, xn01, r0, r1);
            uint32_t xh1 = split_hi(xn10, xn11, r2, r3);
            xfw[yidx] = make_uint4(xh0, xh1, pack_lo(r0, r1), pack_lo(r2, r3));
            uint32_t yh0 = split_hi(yn00, yn01, r0, r1);
            uint32_t yh1 = split_hi(yn10, yn11, r2, r3);
            yfw[yidx] = make_uint4(yh0, yh1, pack_lo(r0, r1), pack_lo(r2, r3));
        }
    }

    // ---- deterministic block reduction (reuse smem after sync) ----
    __syncthreads();
    float* red = (float*)ws;
    red[tid] = sn;  red[256 + tid] = sd;
    __syncthreads();
#pragma unroll
    for (int s = 128; s > 0; s >>= 1) {
        if (tid < s) { red[tid] += red[tid + s]; red[256 + tid] += red[256 + tid + s]; }
        __syncthreads();
    }
    const int cta = mb*4 + nb;
    if (tid == 0) {
        g_partial[cta*2    ] = red[0];
        g_partial[cta*2 + 1] = red[256];
    }

    // ---- merged convergence check: last CTA reduces and gates ----
    __shared__ int islast;
    __threadfence();
    if (tid == 0) islast = (atomicAdd(&g_ctr[it], 1) == NCTAS - 1);
    __syncthreads();
    if (islast) {
        float a = 0.f, b = 0.f;
#pragma unroll
        for (int k = 0; k < 4; ++k) {
            a += g_partial[2*(tid + k*256)    ];
            b += g_partial[2*(tid + k*256) + 1];
        }
        red[tid] = a; red[256 + tid] = b;
        __syncthreads();
#pragma unroll
        for (int s = 128; s > 0; s >>= 1) {
            if (tid < s) { red[tid] += red[tid + s]; red[256 + tid] += red[256 + tid + s]; }
            __syncthreads();
        }
        if (tid == 0) {
            float err = sqrtf(red[0]) / (1e-6f + sqrtf(red[256]));
            if (!(err > 1e-4f)) {
                g_active = 0;
                g_zpar = par;
            }
        }
    }
}

// ---------------- final kernel: out = relu(z @ W + b), z = g_yf[g_zpar] ------
__global__ void __launch_bounds__(256, 3)
final_kernel(float* __restrict__ outp) {
    extern __shared__ __align__(16) uint4 ws[];
    const int tid  = threadIdx.x;
    const int lane = tid & 31;
    const int wid  = tid >> 5;
    const int wm   = wid & 3;
    const int wn   = wid >> 2;
    const int mb   = blockIdx.y;
    const int nb   = blockIdx.x;
    const int par  = g_zpar;

#pragma unroll
    for (int j = 0; j < 16; ++j) {
        int linear = j*256 + tid;
        int l  = linear & 31;
        int r  = linear >> 5;
        int kk = r >> 3, n8l = r & 7;
        ws[linear] = g_wf[kk*1024 + (nb*8 + n8l)*32 + l];
    }
    __syncthreads();

    const uint4* __restrict__ yf = g_yf[par];
    float acc[2][4][4];
#pragma unroll
    for (int mi = 0; mi < 2; ++mi)
#pragma unroll
        for (int ni = 0; ni < 4; ++ni)
#pragma unroll
            for (int q = 0; q < 4; ++q) acc[mi][ni][q] = 0.f;
    const int mt0 = mb*8 + wm*2;
#pragma unroll
    for (int kk = 0; kk < 16; ++kk) {
        uint32_t ah[2][4], al[2][4];
#pragma unroll
        for (int mi = 0; mi < 2; ++mi) {
            int base = (((mt0 + mi)*16 + kk)*2)*32 + lane;
            uint4 u0 = yf[base];
            uint4 u1 = yf[base + 32];
            ah[mi][0] = u0.x; ah[mi][1] = u0.y; ah[mi][2] = u1.x; ah[mi][3] = u1.y;
            al[mi][0] = u0.z; al[mi][1] = u0.w; al[mi][2] = u1.z; al[mi][3] = u1.w;
        }
#pragma unroll
        for (int ni = 0; ni < 4; ++ni) {
            uint4 u = ws[(kk*8 + wn*4 + ni)*32 + lane];
            uint32_t bh[2] = {u.x, u.y};
            uint32_t bl[2] = {u.z, u.w};
#pragma unroll
            for (int mi = 0; mi < 2; ++mi) {
                float* c = acc[mi][ni];
                mma_bf16(c, ah[mi], bh);
                mma_bf16(c, al[mi], bh);
                mma_bf16(c, ah[mi], bl);
            }
        }
    }
    const int t2 = lane & 3, g = lane >> 2;
#pragma unroll
    for (int mi = 0; mi < 2; ++mi) {
        int row0 = mb*128 + wm*32 + mi*16 + g;
#pragma unroll
        for (int ni = 0; ni < 4; ++ni) {
            int k8  = nb*8 + wn*4 + ni;
            int col = k8*8 + t2*2;
            int yidx = (((mt0 + mi)*16 + (k8 >> 1))*2 + (k8 & 1))*32 + lane;
            float b00, b01, b10, b11;
            funpack(g_bf[yidx], b00, b01, b10, b11);
            int gi0 = row0*DIM + col, gi1 = gi0 + 8*DIM;
            *(float2*)(outp + gi0) = make_float2(
                fmaxf(acc[mi][ni][0] + b00, 0.f),
                fmaxf(acc[mi][ni][1] + b01, 0.f));
            *(float2*)(outp + gi1) = make_float2(
                fmaxf(acc[mi][ni][2] + b10, 0.f),
                fmaxf(acc[mi][ni][3] + b11, 0.f));
        }
    }
}

// ---------------- launch ----------------
extern "C" void kernel_launch(void* const* d_in, const int* in_sizes, int n_in,
                              void* d_out, int out_size) {
    const float* x  = (const float*)d_in[0];
    const float* U  = (const float*)d_in[1];
    const float* ub = (const float*)d_in[2];
    const float* A  = (const float*)d_in[3];
    const float* B  = (const float*)d_in[4];
    (void)in_sizes; (void)n_in; (void)out_size;

    static int attr_done = 0;
    if (!attr_done) {
        cudaFuncSetAttribute(bias_tensor,
                             cudaFuncAttributeMaxDynamicSharedMemorySize, WS_BYTES);
        cudaFuncSetAttribute(iter_kernel,
                             cudaFuncAttributeMaxDynamicSharedMemorySize, WS_BYTES);
        cudaFuncSetAttribute(final_kernel,
                             cudaFuncAttributeMaxDynamicSharedMemorySize, WS_BYTES);
        attr_done = 1;
    }

    prep_kernel<<<DIM, DIM>>>(U, A, B);
    dim3 p2grid(16, 32);
    prep2_kernel<<<p2grid, 32>>>();
    flags_kernel<<<1, 64>>>();

    packx_kernel<<<YF_ELEMS/256, 256>>>(x);
    dim3 igrid(4, 256);
    bias_tensor<<<igrid, 256, WS_BYTES>>>(ub);
    start_kernel<<<YF_ELEMS/256, 256>>>();      // body 1: y1 = x1 = relu(b/2)

    float t = 1.6180339887f;                    // t1
    for (int i = 2; i <= MAX_IT; ++i) {
        float tn   = 0.5f * (1.0f + sqrtf(1.0f + 4.0f * t * t));
        float beta = (t - 1.0f) / tn;
        iter_kernel<<<igrid, 256, WS_BYTES>>>(beta, (i - 1) & 1, i - 1);
        t = tn;
    }
    final_kernel<<<igrid, 256, WS_BYTES>>>((float*)d_out);
}